// round 14
// baseline (speedup 1.0000x reference)
#include <cuda_runtime.h>
#include <cuda_bf16.h>
#include <cstdint>
#include <math.h>

typedef unsigned long long u64;

// ---------------------------------------------------------------------------
// Scratch: pre-split bf16 hi/lo operands (allocation-free __device__ globals)
// ---------------------------------------------------------------------------
__device__ __nv_bfloat16 g_xh[64 * 1024 * 256];
__device__ __nv_bfloat16 g_xl[64 * 1024 * 256];
__device__ __nv_bfloat16 g_wh[256 * 256];
__device__ __nv_bfloat16 g_wl[256 * 256];

// ---------------------------------------------------------------------------
// Packed f32x2 helpers (Blackwell sm_103a)
// ---------------------------------------------------------------------------
__device__ __forceinline__ u64 ffma2(u64 a, u64 b, u64 c) {
    u64 d;
    asm("fma.rn.f32x2 %0, %1, %2, %3;" : "=l"(d) : "l"(a), "l"(b), "l"(c));
    return d;
}
__device__ __forceinline__ float2 unpack2(u64 v) {
    float2 f;
    asm("mov.b64 {%0, %1}, %2;" : "=f"(f.x), "=f"(f.y) : "l"(v));
    return f;
}
__device__ __forceinline__ uint32_t smem_u32(const void* p) {
    uint32_t a;
    asm("{ .reg .u64 t; cvta.to.shared.u64 t, %1; cvt.u32.u64 %0, t; }"
        : "=r"(a) : "l"(p));
    return a;
}

// Accurate tanh via ex2.approx (rel err ~2^-22); tanhf under fast-math lowers
// to tanh.approx (abs err ~2^-11) and fails 1e-3 over 1024 recurrent steps.
__device__ __forceinline__ float tanh_acc(float x) {
    float e = __expf(2.0f * x);
    return 1.0f - 2.0f / (e + 1.0f);
}

// ---------------------------------------------------------------------------
// Prep: split fp32 -> (bf16 hi, bf16 lo), streaming, bandwidth-bound.
// ---------------------------------------------------------------------------
__device__ __forceinline__ u64 pack_bf16x4_hi(float4 v) {
    __nv_bfloat16 h0 = __float2bfloat16_rn(v.x), h1 = __float2bfloat16_rn(v.y);
    __nv_bfloat16 h2 = __float2bfloat16_rn(v.z), h3 = __float2bfloat16_rn(v.w);
    return (u64)__bfloat16_as_ushort(h0)
         | ((u64)__bfloat16_as_ushort(h1) << 16)
         | ((u64)__bfloat16_as_ushort(h2) << 32)
         | ((u64)__bfloat16_as_ushort(h3) << 48);
}
__device__ __forceinline__ u64 pack_bf16x4_lo(float4 v) {
    __nv_bfloat16 h0 = __float2bfloat16_rn(v.x), h1 = __float2bfloat16_rn(v.y);
    __nv_bfloat16 h2 = __float2bfloat16_rn(v.z), h3 = __float2bfloat16_rn(v.w);
    __nv_bfloat16 l0 = __float2bfloat16_rn(v.x - __bfloat162float(h0));
    __nv_bfloat16 l1 = __float2bfloat16_rn(v.y - __bfloat162float(h1));
    __nv_bfloat16 l2 = __float2bfloat16_rn(v.z - __bfloat162float(h2));
    __nv_bfloat16 l3 = __float2bfloat16_rn(v.w - __bfloat162float(h3));
    return (u64)__bfloat16_as_ushort(l0)
         | ((u64)__bfloat16_as_ushort(l1) << 16)
         | ((u64)__bfloat16_as_ushort(l2) << 32)
         | ((u64)__bfloat16_as_ushort(l3) << 48);
}

__global__ void __launch_bounds__(256) prep_x_kernel(const float* __restrict__ x) {
    int i = blockIdx.x * 256 + threadIdx.x;        // float4 index, exact cover
    float4 v = ((const float4*)x)[i];
    ((u64*)g_xh)[i] = pack_bf16x4_hi(v);
    ((u64*)g_xl)[i] = pack_bf16x4_lo(v);
}
__global__ void __launch_bounds__(256) prep_w_kernel(const float* __restrict__ w) {
    int i = blockIdx.x * 256 + threadIdx.x;        // 16384 threads cover 65536/4
    float4 v = ((const float4*)w)[i];
    ((u64*)g_wh)[i] = pack_bf16x4_hi(v);
    ((u64*)g_wl)[i] = pack_bf16x4_lo(v);
}

// ---------------------------------------------------------------------------
// Phase 1 (v4): warp-level mma.sync bf16-split GEMM, pre-split operands.
// Identical verified structure to R13 (fragments, swizzle, epilogue), minus
// the inline split: tile staging is now a pure bf16 u64 copy.
// ---------------------------------------------------------------------------
#define XP_AH 0
#define XP_AL (128 * 256)
#define XP_BH (2 * 128 * 256)
#define XP_BL (3 * 128 * 256)
#define XP_SMEM_TOTAL (4 * 128 * 256)   // 131072 bytes

__device__ __forceinline__ void ldsm_x4(uint32_t& r0, uint32_t& r1,
                                        uint32_t& r2, uint32_t& r3, uint32_t a) {
    asm volatile("ldmatrix.sync.aligned.m8n8.x4.shared.b16 {%0,%1,%2,%3}, [%4];"
                 : "=r"(r0), "=r"(r1), "=r"(r2), "=r"(r3) : "r"(a));
}
__device__ __forceinline__ void ldsm_x2(uint32_t& r0, uint32_t& r1, uint32_t a) {
    asm volatile("ldmatrix.sync.aligned.m8n8.x2.shared.b16 {%0,%1}, [%2];"
                 : "=r"(r0), "=r"(r1) : "r"(a));
}
__device__ __forceinline__ void mma_bf16(float* d, const uint32_t* a,
                                         const uint32_t* b) {
    asm volatile(
        "mma.sync.aligned.m16n8k16.row.col.f32.bf16.bf16.f32 "
        "{%0,%1,%2,%3}, {%4,%5,%6,%7}, {%8,%9}, {%0,%1,%2,%3};"
        : "+f"(d[0]), "+f"(d[1]), "+f"(d[2]), "+f"(d[3])
        : "r"(a[0]), "r"(a[1]), "r"(a[2]), "r"(a[3]), "r"(b[0]), "r"(b[1]));
}

// copy a 128x128 bf16 block (k-chunk kc of a 256-wide row-major bf16 src)
// into the XOR-swizzled smem tile
__device__ __forceinline__ void copy_tile(char* sm, int base,
                                          const __nv_bfloat16* src, int kc, int tid) {
    for (int idx = tid; idx < 128 * 32; idx += 256) {
        int row = idx >> 5;
        int c4  = (idx & 31) << 2;          // bf16 index within chunk
        u64 v = *(const u64*)(src + (size_t)row * 256 + kc * 128 + c4);
        uint32_t byte = (uint32_t)(row * 256 + ((c4 * 2) ^ ((row & 7) << 4)));
        *(u64*)(sm + base + byte) = v;
    }
}

__global__ void __launch_bounds__(256, 1)
xproj_mma_kernel(const float* __restrict__ bih, float* __restrict__ C)
{
    extern __shared__ __align__(16) char sm[];
    const int tid  = threadIdx.x;
    const int lane = tid & 31;
    const int wid  = tid >> 5;
    const int wm   = wid & 1;            // 2 M-warps x 64 rows
    const int wn   = wid >> 1;           // 4 N-warps x 32 cols
    const int m0   = blockIdx.x * 128;
    const int n0   = blockIdx.y * 128;
    const uint32_t smb = smem_u32(sm);

    float d[4][4][4];                    // [mi][ni][reg]
#pragma unroll
    for (int mi = 0; mi < 4; mi++)
#pragma unroll
        for (int ni = 0; ni < 4; ni++)
#pragma unroll
            for (int r = 0; r < 4; r++) d[mi][ni][r] = 0.0f;

    const int a_row_l  = (lane & 15);
    const int a_half   = (lane >> 4) * 16;        // bytes
    const int b_row_l  = (lane & 7);
    const int b_half   = ((lane >> 3) & 1) * 16;  // bytes

    for (int kc = 0; kc < 2; kc++) {
        __syncthreads();    // previous chunk's ldmatrix reads complete
        copy_tile(sm, XP_AH, g_xh + (size_t)m0 * 256, kc, tid);
        copy_tile(sm, XP_AL, g_xl + (size_t)m0 * 256, kc, tid);
        copy_tile(sm, XP_BH, g_wh + (size_t)n0 * 256, kc, tid);
        copy_tile(sm, XP_BL, g_wl + (size_t)n0 * 256, kc, tid);
        __syncthreads();

#pragma unroll
        for (int kk = 0; kk < 8; kk++) {
            const int kb = kk * 32;      // 16 bf16 = 32 bytes
            uint32_t ah[4][4], al[4][4], bh[4][2], bl[4][2];
#pragma unroll
            for (int mi = 0; mi < 4; mi++) {
                int row = wm * 64 + mi * 16 + a_row_l;
                uint32_t byte = (uint32_t)(row * 256
                               + ((kb + a_half) ^ ((row & 7) << 4)));
                ldsm_x4(ah[mi][0], ah[mi][1], ah[mi][2], ah[mi][3],
                        smb + XP_AH + byte);
                ldsm_x4(al[mi][0], al[mi][1], al[mi][2], al[mi][3],
                        smb + XP_AL + byte);
            }
#pragma unroll
            for (int ni = 0; ni < 4; ni++) {
                int nrow = wn * 32 + ni * 8 + b_row_l;
                uint32_t byte = (uint32_t)(nrow * 256
                               + ((kb + b_half) ^ ((nrow & 7) << 4)));
                ldsm_x2(bh[ni][0], bh[ni][1], smb + XP_BH + byte);
                ldsm_x2(bl[ni][0], bl[ni][1], smb + XP_BL + byte);
            }
#pragma unroll
            for (int mi = 0; mi < 4; mi++)
#pragma unroll
                for (int ni = 0; ni < 4; ni++) {
                    mma_bf16(d[mi][ni], ah[mi], bh[ni]);   // xh*Wh
                    mma_bf16(d[mi][ni], ah[mi], bl[ni]);   // xh*Wl
                    mma_bf16(d[mi][ni], al[mi], bh[ni]);   // xl*Wh
                }
        }
    }

    // epilogue: direct float2 stores + bias (layout verified in R13)
#pragma unroll
    for (int ni = 0; ni < 4; ni++) {
        const int ncol = n0 + wn * 32 + ni * 8 + (lane & 3) * 2;
        const float2 bv = *(const float2*)(bih + ncol);
#pragma unroll
        for (int mi = 0; mi < 4; mi++) {
            const int mrow = m0 + wm * 64 + mi * 16 + (lane >> 2);
            float2 v0 = make_float2(d[mi][ni][0] + bv.x, d[mi][ni][1] + bv.y);
            float2 v1 = make_float2(d[mi][ni][2] + bv.x, d[mi][ni][3] + bv.y);
            *(float2*)(C + (size_t)mrow * 256 + ncol)       = v0;
            *(float2*)(C + (size_t)(mrow + 8) * 256 + ncol) = v1;
        }
    }
}

// ---------------------------------------------------------------------------
// Phase 2 (v11, UNCHANGED R11 winner): h-mirror scan, X overlapped.
// ---------------------------------------------------------------------------
__device__ __forceinline__ void mbar_wait_cluster(uint32_t addr, uint32_t parity) {
    asm volatile(
        "{\n\t"
        ".reg .pred P;\n\t"
        "LAB_W_%=:\n\t"
        "mbarrier.try_wait.parity.acquire.cluster.shared::cta.b64 P, [%0], %1, 0x989680;\n\t"
        "@P bra.uni LAB_D_%=;\n\t"
        "bra.uni LAB_W_%=;\n\t"
        "LAB_D_%=:\n\t"
        "}"
        :: "r"(addr), "r"(parity) : "memory");
}
__device__ __forceinline__ void mbar_expect(uint32_t addr, uint32_t bytes) {
    asm volatile("mbarrier.arrive.expect_tx.shared.b64 _, [%0], %1;"
                 :: "r"(addr), "r"(bytes) : "memory");
}
__device__ __forceinline__ void send_v4(uint32_t raddr, float s, float s1,
                                        float s2, float s3, uint32_t mbar) {
    asm volatile(
        "st.async.shared::cluster.mbarrier::complete_tx::bytes.v4.b32 "
        "[%0], {%1, %2, %3, %4}, [%5];"
        :: "r"(raddr),
           "r"(__float_as_uint(s)),  "r"(__float_as_uint(s1)),
           "r"(__float_as_uint(s2)), "r"(__float_as_uint(s3)),
           "r"(mbar) : "memory");
}

__global__ void __cluster_dims__(2, 1, 1) __launch_bounds__(256, 1)
rnn_scan_kernel(const float* __restrict__ Whh, const float* __restrict__ bhh,
                float* __restrict__ out)
{
    __shared__ __align__(16) float h_own[2][128];
    __shared__ __align__(16) float h_mir[2][128];
    __shared__ __align__(16) float part[128];
    __shared__ __align__(16) u64 mbar[2];

    const int tid = threadIdx.x;
    uint32_t rank;
    asm("mov.u32 %0, %%cluster_ctarank;" : "=r"(rank));
    const int  batch = blockIdx.x >> 1;
    const int  jl    = tid & 127;
    const bool isB   = (tid >= 128);
    const int  j     = (int)rank * 128 + jl;
    const int  kbase = isB ? ((int)(rank ^ 1u) * 128) : ((int)rank * 128);

    u64 w2[64];
    {
        const ulonglong2* wrow = (const ulonglong2*)(Whh + (size_t)j * 256 + kbase);
#pragma unroll
        for (int i = 0; i < 32; i++) {
            ulonglong2 v = wrow[i];
            w2[2 * i] = v.x; w2[2 * i + 1] = v.y;
        }
    }

    if (tid < 128) {
        h_own[0][tid] = 0.0f; h_own[1][tid] = 0.0f;
        h_mir[0][tid] = 0.0f; h_mir[1][tid] = 0.0f;
    }
    uint32_t mbar_a0 = smem_u32(&mbar[0]);
    uint32_t mbar_a1 = smem_u32(&mbar[1]);
    if (tid == 0) {
        asm volatile("mbarrier.init.shared.b64 [%0], 1;" :: "r"(mbar_a0) : "memory");
        asm volatile("mbarrier.init.shared.b64 [%0], 1;" :: "r"(mbar_a1) : "memory");
    }
    __syncthreads();
    if (tid == 0) {
        asm volatile("mbarrier.arrive.shared.b64 _, [%0];" :: "r"(mbar_a0) : "memory");
        mbar_expect(mbar_a1, 512u);
    }
    asm volatile("barrier.cluster.arrive.aligned;" ::: "memory");
    asm volatile("barrier.cluster.wait.aligned;" ::: "memory");

    uint32_t mir_a = smem_u32(&h_mir[0][0]);
    uint32_t peer = rank ^ 1u;
    uint32_t mir_peer, mbar_peer_base;
    asm("mapa.shared::cluster.u32 %0, %1, %2;" : "=r"(mir_peer)       : "r"(mir_a),   "r"(peer));
    asm("mapa.shared::cluster.u32 %0, %1, %2;" : "=r"(mbar_peer_base) : "r"(mbar_a0), "r"(peer));

    float* outb = out + (size_t)batch * (1024 * 256) + j;
    const float bh = bhh[j];
    float xp_next = isB ? 0.0f : outb[0];

    if (isB) {
        for (int t = 0; t < 1024; t++) {
            const uint32_t p = (uint32_t)(t & 1);
            const uint32_t mb = p ? mbar_a1 : mbar_a0;
            mbar_wait_cluster(mb, (uint32_t)((t >> 1) & 1));
            if (jl == 0 && t < 1022) mbar_expect(mb, 512u);

            const ulonglong2* h4 = (const ulonglong2*)&h_mir[p][0];
            u64 acc0 = 0ull, acc1 = 0ull;
#pragma unroll
            for (int i = 0; i < 16; i++) {
                ulonglong2 va = h4[2 * i];
                acc0 = ffma2(w2[4 * i],     va.x, acc0);
                acc1 = ffma2(w2[4 * i + 1], va.y, acc1);
                ulonglong2 vb = h4[2 * i + 1];
                acc0 = ffma2(w2[4 * i + 2], vb.x, acc0);
                acc1 = ffma2(w2[4 * i + 3], vb.y, acc1);
            }
            float2 a0 = unpack2(acc0), a1 = unpack2(acc1);
            part[jl] = (a0.x + a0.y) + (a1.x + a1.y);
            asm volatile("bar.sync 1, 256;" ::: "memory");
        }
    } else {
        for (int t = 0; t < 1024; t++) {
            const uint32_t p = (uint32_t)(t & 1);

            const ulonglong2* h4 = (const ulonglong2*)&h_own[p][0];
            u64 acc0 = 0ull, acc1 = 0ull;
#pragma unroll
            for (int i = 0; i < 16; i++) {
                ulonglong2 va = h4[2 * i];
                acc0 = ffma2(w2[4 * i],     va.x, acc0);
                acc1 = ffma2(w2[4 * i + 1], va.y, acc1);
                ulonglong2 vb = h4[2 * i + 1];
                acc0 = ffma2(w2[4 * i + 2], vb.x, acc0);
                acc1 = ffma2(w2[4 * i + 3], vb.y, acc1);
            }
            float2 a0 = unpack2(acc0), a1 = unpack2(acc1);
            const float s = (a0.x + a0.y) + (a1.x + a1.y);

            const float xp_cur = xp_next;
            if (t < 1023) xp_next = __ldg(outb + (size_t)(t + 1) * 256);

            asm volatile("bar.sync 1, 256;" ::: "memory");

            const float tot = s + part[jl] + xp_cur + bh;
            const float h = tanh_acc(tot);
            h_own[p ^ 1][jl] = h;

            if (t < 1023) {
                const float u1 = __shfl_down_sync(0xFFFFFFFFu, h, 1);
                const float u2 = __shfl_down_sync(0xFFFFFFFFu, h, 2);
                const float u3 = __shfl_down_sync(0xFFFFFFFFu, h, 3);
                if ((tid & 3) == 0)
                    send_v4(mir_peer + (((p ^ 1u) << 9) | ((uint32_t)jl << 2)),
                            h, u1, u2, u3,
                            mbar_peer_base + ((p ^ 1u) << 3));
            }
            outb[(size_t)t * 256] = h;

            asm volatile("bar.sync 2, 128;" ::: "memory");
        }
    }

    asm volatile("barrier.cluster.arrive.aligned;" ::: "memory");
    asm volatile("barrier.cluster.wait.aligned;" ::: "memory");
}

// ---------------------------------------------------------------------------
// Harness entry. Inputs: x, W_ih, W_hh, b_ih, b_hh. Output fp32 [B,T,H].
// prep (bf16 split) -> mma.sync GEMM into d_out -> scan overwrites in place.
// ---------------------------------------------------------------------------
extern "C" void kernel_launch(void* const* d_in, const int* in_sizes, int n_in,
                              void* d_out, int out_size)
{
    const float* x   = (const float*)d_in[0];
    const float* Wih = (const float*)d_in[1];
    const float* Whh = (const float*)d_in[2];
    const float* bih = (const float*)d_in[3];
    const float* bhh = (const float*)d_in[4];
    float* out = (float*)d_out;

    static bool attr_set = false;
    if (!attr_set) {
        cudaFuncSetAttribute(xproj_mma_kernel,
                             cudaFuncAttributeMaxDynamicSharedMemorySize,
                             XP_SMEM_TOTAL);
        attr_set = true;
    }

    // Phase 0: streaming bf16 hi/lo split (bandwidth-bound)
    prep_x_kernel<<<16384, 256>>>(x);
    prep_w_kernel<<<64, 256>>>(Wih);

    // Phase 1: tensor-core x_proj GEMM (512 M-tiles x 2 N-tiles)
    dim3 gg(512, 2);
    xproj_mma_kernel<<<gg, 256, XP_SMEM_TOTAL>>>(bih, out);

    // Phase 2: recurrent scan (64 clusters x 2 CTAs)
    rnn_scan_kernel<<<128, 256>>>(Whh, bhh, out);
}

// round 16
// speedup vs baseline: 1.1371x; 1.1371x over previous
#include <cuda_runtime.h>
#include <cuda_fp16.h>
#include <cstdint>
#include <math.h>

typedef unsigned long long u64;

// ---------------------------------------------------------------------------
// Packed f32x2 helpers (Blackwell sm_103a)
// ---------------------------------------------------------------------------
__device__ __forceinline__ u64 ffma2(u64 a, u64 b, u64 c) {
    u64 d;
    asm("fma.rn.f32x2 %0, %1, %2, %3;" : "=l"(d) : "l"(a), "l"(b), "l"(c));
    return d;
}
__device__ __forceinline__ float2 unpack2(u64 v) {
    float2 f;
    asm("mov.b64 {%0, %1}, %2;" : "=f"(f.x), "=f"(f.y) : "l"(v));
    return f;
}
__device__ __forceinline__ uint32_t smem_u32(const void* p) {
    uint32_t a;
    asm("{ .reg .u64 t; cvta.to.shared.u64 t, %1; cvt.u32.u64 %0, t; }"
        : "=r"(a) : "l"(p));
    return a;
}

// Accurate tanh via ex2.approx (rel err ~2^-22); tanhf under fast-math lowers
// to tanh.approx (abs err ~2^-11) and fails 1e-3 over 1024 recurrent steps.
__device__ __forceinline__ float tanh_acc(float x) {
    float e = __expf(2.0f * x);
    return 1.0f - 2.0f / (e + 1.0f);
}

// ---------------------------------------------------------------------------
// Phase 1 (v5): fp16 single-term mma.sync GEMM.
// C[m][n] = x[m,:]·W[n,:] + b[n], computed as fp16(x)·fp16(W) with fp32
// accumulate. mma.sync fp16 products are EXACT in fp32 accumulation; only
// representation rounding (2^-12 RMS) contributes -> xp rel err ~2e-4,
// final ~3e-4 < 1e-3 threshold. 3x fewer MMAs than the bf16 3-term split
// (the legacy HMMA path is MMA-issue-bound at ~512 MAC/cyc/SM).
//
// Per CTA: 128x128 output, K=256 FULLY RESIDENT (A 64KB + B 64KB fp16).
// One staging pass (inline fp32->fp16 cvt), one __syncthreads, 16 k-steps.
// Fragments/swizzle/epilogue identical to the R13-verified layout with
// row stride 512B (same mod-128 bank pattern).
// ---------------------------------------------------------------------------
#define XP_A 0
#define XP_B 65536
#define XP_SMEM_TOTAL 131072

__device__ __forceinline__ void ldsm_x4(uint32_t& r0, uint32_t& r1,
                                        uint32_t& r2, uint32_t& r3, uint32_t a) {
    asm volatile("ldmatrix.sync.aligned.m8n8.x4.shared.b16 {%0,%1,%2,%3}, [%4];"
                 : "=r"(r0), "=r"(r1), "=r"(r2), "=r"(r3) : "r"(a));
}
__device__ __forceinline__ void ldsm_x2(uint32_t& r0, uint32_t& r1, uint32_t a) {
    asm volatile("ldmatrix.sync.aligned.m8n8.x2.shared.b16 {%0,%1}, [%2];"
                 : "=r"(r0), "=r"(r1) : "r"(a));
}
__device__ __forceinline__ void mma_fp16(float* d, const uint32_t* a,
                                         const uint32_t* b) {
    asm volatile(
        "mma.sync.aligned.m16n8k16.row.col.f32.f16.f16.f32 "
        "{%0,%1,%2,%3}, {%4,%5,%6,%7}, {%8,%9}, {%0,%1,%2,%3};"
        : "+f"(d[0]), "+f"(d[1]), "+f"(d[2]), "+f"(d[3])
        : "r"(a[0]), "r"(a[1]), "r"(a[2]), "r"(a[3]), "r"(b[0]), "r"(b[1]));
}

// stage a 128x256 fp32 block as fp16 into the XOR-swizzled smem tile
__device__ __forceinline__ void stage_tile_fp16(char* sm, int base,
                                                const float* src, int tid) {
    for (int idx = tid; idx < 128 * 64; idx += 256) {
        int row = idx >> 6;
        int c   = (idx & 63) << 2;               // float index 0..252
        float4 v = *(const float4*)(src + (size_t)row * 256 + c);
        u64 val = (u64)__half_as_ushort(__float2half_rn(v.x))
                | ((u64)__half_as_ushort(__float2half_rn(v.y)) << 16)
                | ((u64)__half_as_ushort(__float2half_rn(v.z)) << 32)
                | ((u64)__half_as_ushort(__float2half_rn(v.w)) << 48);
        uint32_t byte = (uint32_t)(row * 512 + ((c * 2) ^ ((row & 7) << 4)));
        *(u64*)(sm + base + byte) = val;
    }
}

__global__ void __launch_bounds__(256, 1)
xproj_fp16_kernel(const float* __restrict__ X, const float* __restrict__ Wih,
                  const float* __restrict__ bih, float* __restrict__ C)
{
    extern __shared__ __align__(16) char sm[];
    const int tid  = threadIdx.x;
    const int lane = tid & 31;
    const int wid  = tid >> 5;
    const int wm   = wid & 1;            // 2 M-warps x 64 rows
    const int wn   = wid >> 1;           // 4 N-warps x 32 cols
    const int m0   = blockIdx.x * 128;
    const int n0   = blockIdx.y * 128;
    const uint32_t smb = smem_u32(sm);

    float d[4][4][4];                    // [mi][ni][reg]
#pragma unroll
    for (int mi = 0; mi < 4; mi++)
#pragma unroll
        for (int ni = 0; ni < 4; ni++)
#pragma unroll
            for (int r = 0; r < 4; r++) d[mi][ni][r] = 0.0f;

    // stage both tiles (fp32 -> fp16 inline), K=256 resident
    stage_tile_fp16(sm, XP_A, X   + (size_t)m0 * 256, tid);
    stage_tile_fp16(sm, XP_B, Wih + (size_t)n0 * 256, tid);
    __syncthreads();

    const int a_row_l = (lane & 15);
    const int a_half  = (lane >> 4) * 16;        // bytes
    const int b_row_l = (lane & 7);
    const int b_half  = ((lane >> 3) & 1) * 16;  // bytes

#pragma unroll
    for (int kk = 0; kk < 16; kk++) {
        const int kb = kk * 32;          // 16 fp16 = 32 bytes
        uint32_t af[4][4], bf[4][2];
#pragma unroll
        for (int mi = 0; mi < 4; mi++) {
            int row = wm * 64 + mi * 16 + a_row_l;
            uint32_t byte = (uint32_t)(row * 512
                           + ((kb + a_half) ^ ((row & 7) << 4)));
            ldsm_x4(af[mi][0], af[mi][1], af[mi][2], af[mi][3],
                    smb + XP_A + byte);
        }
#pragma unroll
        for (int ni = 0; ni < 4; ni++) {
            int nrow = wn * 32 + ni * 8 + b_row_l;
            uint32_t byte = (uint32_t)(nrow * 512
                           + ((kb + b_half) ^ ((nrow & 7) << 4)));
            ldsm_x2(bf[ni][0], bf[ni][1], smb + XP_B + byte);
        }
#pragma unroll
        for (int mi = 0; mi < 4; mi++)
#pragma unroll
            for (int ni = 0; ni < 4; ni++)
                mma_fp16(d[mi][ni], af[mi], bf[ni]);
    }

    // epilogue: direct float2 stores + bias (layout verified in R13)
#pragma unroll
    for (int ni = 0; ni < 4; ni++) {
        const int ncol = n0 + wn * 32 + ni * 8 + (lane & 3) * 2;
        const float2 bv = *(const float2*)(bih + ncol);
#pragma unroll
        for (int mi = 0; mi < 4; mi++) {
            const int mrow = m0 + wm * 64 + mi * 16 + (lane >> 2);
            float2 v0 = make_float2(d[mi][ni][0] + bv.x, d[mi][ni][1] + bv.y);
            float2 v1 = make_float2(d[mi][ni][2] + bv.x, d[mi][ni][3] + bv.y);
            *(float2*)(C + (size_t)mrow * 256 + ncol)       = v0;
            *(float2*)(C + (size_t)(mrow + 8) * 256 + ncol) = v1;
        }
    }
}

// ---------------------------------------------------------------------------
// Phase 2 (v11, UNCHANGED R11 winner): h-mirror scan, X overlapped.
// ---------------------------------------------------------------------------
__device__ __forceinline__ void mbar_wait_cluster(uint32_t addr, uint32_t parity) {
    asm volatile(
        "{\n\t"
        ".reg .pred P;\n\t"
        "LAB_W_%=:\n\t"
        "mbarrier.try_wait.parity.acquire.cluster.shared::cta.b64 P, [%0], %1, 0x989680;\n\t"
        "@P bra.uni LAB_D_%=;\n\t"
        "bra.uni LAB_W_%=;\n\t"
        "LAB_D_%=:\n\t"
        "}"
        :: "r"(addr), "r"(parity) : "memory");
}
__device__ __forceinline__ void mbar_expect(uint32_t addr, uint32_t bytes) {
    asm volatile("mbarrier.arrive.expect_tx.shared.b64 _, [%0], %1;"
                 :: "r"(addr), "r"(bytes) : "memory");
}
__device__ __forceinline__ void send_v4(uint32_t raddr, float s, float s1,
                                        float s2, float s3, uint32_t mbar) {
    asm volatile(
        "st.async.shared::cluster.mbarrier::complete_tx::bytes.v4.b32 "
        "[%0], {%1, %2, %3, %4}, [%5];"
        :: "r"(raddr),
           "r"(__float_as_uint(s)),  "r"(__float_as_uint(s1)),
           "r"(__float_as_uint(s2)), "r"(__float_as_uint(s3)),
           "r"(mbar) : "memory");
}

__global__ void __cluster_dims__(2, 1, 1) __launch_bounds__(256, 1)
rnn_scan_kernel(const float* __restrict__ Whh, const float* __restrict__ bhh,
                float* __restrict__ out)
{
    __shared__ __align__(16) float h_own[2][128];
    __shared__ __align__(16) float h_mir[2][128];
    __shared__ __align__(16) float part[128];
    __shared__ __align__(16) u64 mbar[2];

    const int tid = threadIdx.x;
    uint32_t rank;
    asm("mov.u32 %0, %%cluster_ctarank;" : "=r"(rank));
    const int  batch = blockIdx.x >> 1;
    const int  jl    = tid & 127;
    const bool isB   = (tid >= 128);
    const int  j     = (int)rank * 128 + jl;
    const int  kbase = isB ? ((int)(rank ^ 1u) * 128) : ((int)rank * 128);

    u64 w2[64];
    {
        const ulonglong2* wrow = (const ulonglong2*)(Whh + (size_t)j * 256 + kbase);
#pragma unroll
        for (int i = 0; i < 32; i++) {
            ulonglong2 v = wrow[i];
            w2[2 * i] = v.x; w2[2 * i + 1] = v.y;
        }
    }

    if (tid < 128) {
        h_own[0][tid] = 0.0f; h_own[1][tid] = 0.0f;
        h_mir[0][tid] = 0.0f; h_mir[1][tid] = 0.0f;
    }
    uint32_t mbar_a0 = smem_u32(&mbar[0]);
    uint32_t mbar_a1 = smem_u32(&mbar[1]);
    if (tid == 0) {
        asm volatile("mbarrier.init.shared.b64 [%0], 1;" :: "r"(mbar_a0) : "memory");
        asm volatile("mbarrier.init.shared.b64 [%0], 1;" :: "r"(mbar_a1) : "memory");
    }
    __syncthreads();
    if (tid == 0) {
        asm volatile("mbarrier.arrive.shared.b64 _, [%0];" :: "r"(mbar_a0) : "memory");
        mbar_expect(mbar_a1, 512u);
    }
    asm volatile("barrier.cluster.arrive.aligned;" ::: "memory");
    asm volatile("barrier.cluster.wait.aligned;" ::: "memory");

    uint32_t mir_a = smem_u32(&h_mir[0][0]);
    uint32_t peer = rank ^ 1u;
    uint32_t mir_peer, mbar_peer_base;
    asm("mapa.shared::cluster.u32 %0, %1, %2;" : "=r"(mir_peer)       : "r"(mir_a),   "r"(peer));
    asm("mapa.shared::cluster.u32 %0, %1, %2;" : "=r"(mbar_peer_base) : "r"(mbar_a0), "r"(peer));

    float* outb = out + (size_t)batch * (1024 * 256) + j;
    const float bh = bhh[j];
    float xp_next = isB ? 0.0f : outb[0];

    if (isB) {
        for (int t = 0; t < 1024; t++) {
            const uint32_t p = (uint32_t)(t & 1);
            const uint32_t mb = p ? mbar_a1 : mbar_a0;
            mbar_wait_cluster(mb, (uint32_t)((t >> 1) & 1));
            if (jl == 0 && t < 1022) mbar_expect(mb, 512u);

            const ulonglong2* h4 = (const ulonglong2*)&h_mir[p][0];
            u64 acc0 = 0ull, acc1 = 0ull;
#pragma unroll
            for (int i = 0; i < 16; i++) {
                ulonglong2 va = h4[2 * i];
                acc0 = ffma2(w2[4 * i],     va.x, acc0);
                acc1 = ffma2(w2[4 * i + 1], va.y, acc1);
                ulonglong2 vb = h4[2 * i + 1];
                acc0 = ffma2(w2[4 * i + 2], vb.x, acc0);
                acc1 = ffma2(w2[4 * i + 3], vb.y, acc1);
            }
            float2 a0 = unpack2(acc0), a1 = unpack2(acc1);
            part[jl] = (a0.x + a0.y) + (a1.x + a1.y);
            asm volatile("bar.sync 1, 256;" ::: "memory");
        }
    } else {
        for (int t = 0; t < 1024; t++) {
            const uint32_t p = (uint32_t)(t & 1);

            const ulonglong2* h4 = (const ulonglong2*)&h_own[p][0];
            u64 acc0 = 0ull, acc1 = 0ull;
#pragma unroll
            for (int i = 0; i < 16; i++) {
                ulonglong2 va = h4[2 * i];
                acc0 = ffma2(w2[4 * i],     va.x, acc0);
                acc1 = ffma2(w2[4 * i + 1], va.y, acc1);
                ulonglong2 vb = h4[2 * i + 1];
                acc0 = ffma2(w2[4 * i + 2], vb.x, acc0);
                acc1 = ffma2(w2[4 * i + 3], vb.y, acc1);
            }
            float2 a0 = unpack2(acc0), a1 = unpack2(acc1);
            const float s = (a0.x + a0.y) + (a1.x + a1.y);

            const float xp_cur = xp_next;
            if (t < 1023) xp_next = __ldg(outb + (size_t)(t + 1) * 256);

            asm volatile("bar.sync 1, 256;" ::: "memory");

            const float tot = s + part[jl] + xp_cur + bh;
            const float h = tanh_acc(tot);
            h_own[p ^ 1][jl] = h;

            if (t < 1023) {
                const float u1 = __shfl_down_sync(0xFFFFFFFFu, h, 1);
                const float u2 = __shfl_down_sync(0xFFFFFFFFu, h, 2);
                const float u3 = __shfl_down_sync(0xFFFFFFFFu, h, 3);
                if ((tid & 3) == 0)
                    send_v4(mir_peer + (((p ^ 1u) << 9) | ((uint32_t)jl << 2)),
                            h, u1, u2, u3,
                            mbar_peer_base + ((p ^ 1u) << 3));
            }
            outb[(size_t)t * 256] = h;

            asm volatile("bar.sync 2, 128;" ::: "memory");
        }
    }

    asm volatile("barrier.cluster.arrive.aligned;" ::: "memory");
    asm volatile("barrier.cluster.wait.aligned;" ::: "memory");
}

// ---------------------------------------------------------------------------
// Harness entry. Inputs: x, W_ih, W_hh, b_ih, b_hh. Output fp32 [B,T,H].
// fp16 mma.sync GEMM into d_out -> scan overwrites in place.
// ---------------------------------------------------------------------------
extern "C" void kernel_launch(void* const* d_in, const int* in_sizes, int n_in,
                              void* d_out, int out_size)
{
    const float* x   = (const float*)d_in[0];
    const float* Wih = (const float*)d_in[1];
    const float* Whh = (const float*)d_in[2];
    const float* bih = (const float*)d_in[3];
    const float* bhh = (const float*)d_in[4];
    float* out = (float*)d_out;

    static bool attr_set = false;
    if (!attr_set) {
        cudaFuncSetAttribute(xproj_fp16_kernel,
                             cudaFuncAttributeMaxDynamicSharedMemorySize,
                             XP_SMEM_TOTAL);
        attr_set = true;
    }

    // Phase 1: fp16 tensor-core x_proj GEMM (512 M-tiles x 2 N-tiles)
    dim3 gg(512, 2);
    xproj_fp16_kernel<<<gg, 256, XP_SMEM_TOTAL>>>(x, Wih, bih, out);

    // Phase 2: recurrent scan (64 clusters x 2 CTAs)
    rnn_scan_kernel<<<128, 256>>>(Whh, bhh, out);
}